// round 5
// baseline (speedup 1.0000x reference)
#include <cuda_runtime.h>
#include <cuda_fp16.h>
#include <math.h>

#define NF 128
#define HID 64
#define MAXN 50000
#define MAXE 800000
#define MAXG 64
#define BN_EPS 1e-5f

// ---- static scratch ----
__device__ int    g_cnt   [MAXN];
__device__ int    g_rowptr[MAXN];
__device__ int    g_cursor[MAXN];
__device__ float  g_dinv  [MAXN];
__device__ int    g_csr   [MAXE];          // src indices grouped by dst
__device__ float  g_id    [MAXN * HID];    // fp32 input projection (residual)
__device__ __half g_hph   [MAXN * HID];    // fp16 pre-scaled GEMM output
__device__ float  g_h     [MAXN * HID];    // fp32 layer state
__device__ float  g_sums  [MAXG * HID];
__device__ float  g_cnts  [MAXG];

__device__ __forceinline__ void red_add_v2(float* addr, float a, float b) {
    asm volatile("red.global.add.v2.f32 [%0], {%1,%2};"
                 :: "l"(addr), "f"(a), "f"(b) : "memory");
}

__device__ __forceinline__ void mma16816(float& d0, float& d1, float& d2, float& d3,
                                         unsigned a0, unsigned a1, unsigned a2, unsigned a3,
                                         unsigned b0, unsigned b1) {
    asm volatile("mma.sync.aligned.m16n8k16.row.col.f32.f16.f16.f32 "
                 "{%0,%1,%2,%3}, {%4,%5,%6,%7}, {%8,%9}, {%0,%1,%2,%3};"
                 : "+f"(d0), "+f"(d1), "+f"(d2), "+f"(d3)
                 : "r"(a0), "r"(a1), "r"(a2), "r"(a3), "r"(b0), "r"(b1));
}

// split a float into hi+lo fp16 pair (x ~= hi + lo, error ~2^-22)
__device__ __forceinline__ void split2(float x, float y, __half2& hi, __half2& lo) {
    hi = __floats2half2_rn(x, y);
    float2 h = __half22float2(hi);
    lo = __floats2half2_rn(x - h.x, y - h.y);
}

// ---------------- setup ----------------
__global__ void k_init(int N) {
    int i = blockIdx.x * blockDim.x + threadIdx.x;
    if (i < N) g_cnt[i] = 0;
}

__global__ void k_hist(const int* __restrict__ dst, int E, int G) {
    int i = blockIdx.x * blockDim.x + threadIdx.x;
    if (i < E) atomicAdd(&g_cnt[dst[i]], 1);
    if (i < G * HID) g_sums[i] = 0.0f;
    if (i < G) g_cnts[i] = 0.0f;
}

// single-block exclusive scan of g_cnt -> rowptr/cursor + dinv
__global__ void k_scanall(int N) {
    __shared__ int sh[1024];
    const int t = threadIdx.x;
    const int per = (N + 1023) / 1024;
    const int base = t * per;
    int s = 0;
    for (int i = 0; i < per; i++) {
        int idx = base + i;
        if (idx < N) s += g_cnt[idx];
    }
    sh[t] = s;
    __syncthreads();
    for (int off = 1; off < 1024; off <<= 1) {
        int v = (t >= off) ? sh[t - off] : 0;
        __syncthreads();
        sh[t] += v;
        __syncthreads();
    }
    int run = sh[t] - s;   // exclusive prefix of this thread's chunk
    for (int i = 0; i < per; i++) {
        int idx = base + i;
        if (idx < N) {
            int c = g_cnt[idx];
            g_rowptr[idx] = run;
            g_cursor[idx] = run;
            g_dinv[idx]   = rsqrtf((float)c + 1.0f);  // +1 self-loop
            run += c;
        }
    }
}

__global__ void k_fill(const int* __restrict__ src, const int* __restrict__ dst, int E) {
    int e = blockIdx.x * blockDim.x + threadIdx.x;
    if (e < E) {
        int d = dst[e];
        int pos = atomicAdd(&g_cursor[d], 1);
        g_csr[pos] = src[e];
    }
}

// ------- split-fp16 tensor-core GEMM: out[N,64] = X[N,K] @ W[64,K]^T -------
// x = xh + xl (both fp16). acc += Ah*Bh + Ah*Bl + Al*Bh  => ~fp32 accuracy.
// Block: 256 threads, tile 128 nodes x 64 feats, full K resident in smem.
template <int K, bool HOUT>
__global__ void __launch_bounds__(256) k_mma(const float* __restrict__ X,
                                             const float* __restrict__ W,
                                             void* __restrict__ outp, int N) {
    constexpr int RS = K + 8;                 // padded row stride (halves)
    extern __shared__ __half sm[];
    __half* Xh = sm;                          // [128][RS]
    __half* Xl = Xh + 128 * RS;
    __half* Wh = Xl + 128 * RS;               // [64][RS]
    __half* Wl = Wh + 64 * RS;

    const int tid = threadIdx.x;
    const int nbase = blockIdx.x * 128;

    // stage X tile (fp32 -> hi/lo fp16)
    constexpr int XF4 = 128 * K / 4;
    for (int i = tid; i < XF4; i += 256) {
        int node = i / (K / 4);
        int k = (i - node * (K / 4)) * 4;
        int gn = nbase + node;
        float4 v = (gn < N) ? *(const float4*)(X + (size_t)gn * K + k)
                            : make_float4(0.f, 0.f, 0.f, 0.f);
        __half2 h0, l0, h1, l1;
        split2(v.x, v.y, h0, l0);
        split2(v.z, v.w, h1, l1);
        __half2* ph = (__half2*)(Xh + node * RS + k);
        __half2* pl = (__half2*)(Xl + node * RS + k);
        ph[0] = h0; ph[1] = h1;
        pl[0] = l0; pl[1] = l1;
    }
    // stage W (fp32 -> hi/lo fp16)
    constexpr int WF4 = 64 * K / 4;
    for (int i = tid; i < WF4; i += 256) {
        int n = i / (K / 4);
        int k = (i - n * (K / 4)) * 4;
        float4 v = *(const float4*)(W + (size_t)n * K + k);
        __half2 h0, l0, h1, l1;
        split2(v.x, v.y, h0, l0);
        split2(v.z, v.w, h1, l1);
        __half2* ph = (__half2*)(Wh + n * RS + k);
        __half2* pl = (__half2*)(Wl + n * RS + k);
        ph[0] = h0; ph[1] = h1;
        pl[0] = l0; pl[1] = l1;
    }
    __syncthreads();

    const int warp = tid >> 5;
    const int lane = tid & 31;
    const int r  = lane >> 2;       // 0..7
    const int kc = (lane & 3) * 2;  // 0,2,4,6
    const int m0 = warp * 16;

    float acc[8][4];
#pragma unroll
    for (int nt = 0; nt < 8; nt++)
#pragma unroll
        for (int j = 0; j < 4; j++) acc[nt][j] = 0.f;

#pragma unroll
    for (int k0 = 0; k0 < K; k0 += 16) {
        const int ra0 = (m0 + r)     * RS + k0 + kc;
        const int ra1 = (m0 + r + 8) * RS + k0 + kc;
        unsigned ah0 = *(const unsigned*)(Xh + ra0);
        unsigned ah1 = *(const unsigned*)(Xh + ra1);
        unsigned ah2 = *(const unsigned*)(Xh + ra0 + 8);
        unsigned ah3 = *(const unsigned*)(Xh + ra1 + 8);
        unsigned al0 = *(const unsigned*)(Xl + ra0);
        unsigned al1 = *(const unsigned*)(Xl + ra1);
        unsigned al2 = *(const unsigned*)(Xl + ra0 + 8);
        unsigned al3 = *(const unsigned*)(Xl + ra1 + 8);
#pragma unroll
        for (int nt = 0; nt < 8; nt++) {
            const int rb = (nt * 8 + r) * RS + k0 + kc;
            unsigned bh0 = *(const unsigned*)(Wh + rb);
            unsigned bh1 = *(const unsigned*)(Wh + rb + 8);
            unsigned bl0 = *(const unsigned*)(Wl + rb);
            unsigned bl1 = *(const unsigned*)(Wl + rb + 8);
            mma16816(acc[nt][0], acc[nt][1], acc[nt][2], acc[nt][3],
                     ah0, ah1, ah2, ah3, bh0, bh1);
            mma16816(acc[nt][0], acc[nt][1], acc[nt][2], acc[nt][3],
                     ah0, ah1, ah2, ah3, bl0, bl1);
            mma16816(acc[nt][0], acc[nt][1], acc[nt][2], acc[nt][3],
                     al0, al1, al2, al3, bh0, bh1);
        }
    }

    const int row0 = nbase + m0 + r;
    const int row1 = row0 + 8;
    const int nc = kc;   // output column pair offset = 2*(lane&3)
    if (HOUT) {
        __half* O = (__half*)outp;
        float s0 = (row0 < N) ? g_dinv[row0] : 0.f;
        float s1 = (row1 < N) ? g_dinv[row1] : 0.f;
#pragma unroll
        for (int nt = 0; nt < 8; nt++) {
            int col = nt * 8 + nc;
            if (row0 < N)
                *(__half2*)(O + (size_t)row0 * HID + col) =
                    __floats2half2_rn(acc[nt][0] * s0, acc[nt][1] * s0);
            if (row1 < N)
                *(__half2*)(O + (size_t)row1 * HID + col) =
                    __floats2half2_rn(acc[nt][2] * s1, acc[nt][3] * s1);
        }
    } else {
        float* O = (float*)outp;
#pragma unroll
        for (int nt = 0; nt < 8; nt++) {
            int col = nt * 8 + nc;
            if (row0 < N)
                *(float2*)(O + (size_t)row0 * HID + col) = make_float2(acc[nt][0], acc[nt][1]);
            if (row1 < N)
                *(float2*)(O + (size_t)row1 * HID + col) = make_float2(acc[nt][2], acc[nt][3]);
        }
    }
}

// ---------------- fused aggregate + epilogue (+ optional pool) -----------
__global__ void __launch_bounds__(256) k_agg(
        const __half* __restrict__ hp, const float* __restrict__ resid,
        const float* __restrict__ bias, const float* __restrict__ gamma,
        const float* __restrict__ beta, const float* __restrict__ mean,
        const float* __restrict__ var,
        float* __restrict__ hout, const int* __restrict__ batch, int N) {
    int n = (blockIdx.x * blockDim.x + threadIdx.x) >> 5;
    if (n >= N) return;
    const int lane = threadIdx.x & 31;
    const int f = lane * 2;

    const int  start = g_rowptr[n];
    const int  len   = g_cnt[n];
    const int* cs    = g_csr + start;

    float ax = 0.f, ay = 0.f, bx = 0.f, by = 0.f;
    int j = 0;
    for (; j + 4 <= len; j += 4) {
        int s0 = cs[j], s1 = cs[j + 1], s2 = cs[j + 2], s3 = cs[j + 3];
        float2 v0 = __half22float2(*(const __half2*)(hp + (size_t)s0 * HID + f));
        float2 v1 = __half22float2(*(const __half2*)(hp + (size_t)s1 * HID + f));
        float2 v2 = __half22float2(*(const __half2*)(hp + (size_t)s2 * HID + f));
        float2 v3 = __half22float2(*(const __half2*)(hp + (size_t)s3 * HID + f));
        ax += v0.x + v1.x;
        ay += v0.y + v1.y;
        bx += v2.x + v3.x;
        by += v2.y + v3.y;
    }
    for (; j < len; j++) {
        int s = cs[j];
        float2 v = __half22float2(*(const __half2*)(hp + (size_t)s * HID + f));
        ax += v.x;
        ay += v.y;
    }
    ax += bx; ay += by;

    float di = g_dinv[n];
    float2 p = __half22float2(*(const __half2*)(hp + (size_t)n * HID + f));
    float vx = (ax + p.x) * di + bias[f];
    float vy = (ay + p.y) * di + bias[f + 1];
    vx = (vx - mean[f])     * (gamma[f]     * rsqrtf(var[f]     + BN_EPS)) + beta[f];
    vy = (vy - mean[f + 1]) * (gamma[f + 1] * rsqrtf(var[f + 1] + BN_EPS)) + beta[f + 1];
    vx = fmaxf(vx, 0.f);
    vy = fmaxf(vy, 0.f);
    if (resid) {
        float2 r = *(const float2*)(resid + (size_t)n * HID + f);
        vx += r.x; vy += r.y;
    }
    if (hout)
        *(float2*)(hout + (size_t)n * HID + f) = make_float2(vx, vy);
    if (batch) {
        int g = batch[n];
        red_add_v2(&g_sums[(size_t)g * HID + f], vx, vy);
        if (lane == 0) atomicAdd(&g_cnts[g], 1.0f);
    }
}

// ---------------- final linear ----------------
__global__ void k_final(const float* __restrict__ lin_w, const float* __restrict__ lin_b,
                        float* __restrict__ out, int G) {
    int g = blockIdx.x * blockDim.x + threadIdx.x;
    if (g >= G) return;
    float c = fmaxf(g_cnts[g], 1.0f);
    float acc = 0.f;
#pragma unroll
    for (int f = 0; f < HID; f++) acc += g_sums[g * HID + f] * lin_w[f];
    out[g] = acc / c + lin_b[0];
}

// ---------------- host launcher ----------------
extern "C" void kernel_launch(void* const* d_in, const int* in_sizes, int n_in,
                              void* d_out, int out_size) {
    const float* x     = (const float*)d_in[0];
    const int*   ei    = (const int*)  d_in[1];
    const int*   batch = (const int*)  d_in[2];
    const float* W_in  = (const float*)d_in[3];
    const float* W1    = (const float*)d_in[4];
    const float* b1    = (const float*)d_in[5];
    const float* Ws    = (const float*)d_in[6];
    const float* bs    = (const float*)d_in[7];
    const float* bn_g  = (const float*)d_in[8];
    const float* bn_b  = (const float*)d_in[9];
    const float* bn_m  = (const float*)d_in[10];
    const float* bn_v  = (const float*)d_in[11];
    const float* lin_w = (const float*)d_in[12];
    const float* lin_b = (const float*)d_in[13];
    float* out = (float*)d_out;

    const int N = in_sizes[0] / NF;
    const int E = in_sizes[1] / 2;
    const int G = out_size;
    const int* src = ei;
    const int* dst = ei + E;

    float  *p_id, *p_h;
    __half *p_hph;
    cudaGetSymbolAddress((void**)&p_id,  g_id);
    cudaGetSymbolAddress((void**)&p_hph, g_hph);
    cudaGetSymbolAddress((void**)&p_h,   g_h);

    // dynamic smem sizes: 2*(128+64)*(K+8)*2 bytes
    const int smem128 = 2 * (128 + 64) * (128 + 8) * 2;   // 104448 B
    const int smem64  = 2 * (128 + 64) * (64 + 8) * 2;    // 55296 B
    static bool attr_done = false;
    if (!attr_done) {
        cudaFuncSetAttribute(k_mma<NF, false>, cudaFuncAttributeMaxDynamicSharedMemorySize, smem128);
        cudaFuncSetAttribute(k_mma<NF, true >, cudaFuncAttributeMaxDynamicSharedMemorySize, smem128);
        cudaFuncSetAttribute(k_mma<HID, true>, cudaFuncAttributeMaxDynamicSharedMemorySize, smem64);
        attr_done = true;
    }

    const int thr = 256;
    k_init   <<<(N + thr - 1) / thr, thr>>>(N);
    k_hist   <<<(E + thr - 1) / thr, thr>>>(dst, E, G);
    k_scanall<<<1, 1024>>>(N);
    k_fill   <<<(E + thr - 1) / thr, thr>>>(src, dst, E);

    const int gemmB = (N + 127) / 128;
    k_mma<NF, false><<<gemmB, 256, smem128>>>(x, W_in, p_id,  N);
    k_mma<NF, true ><<<gemmB, 256, smem128>>>(x, W1,   p_hph, N);

    const int aggB = (N * 32 + thr - 1) / thr;

    for (int layer = 0; layer < 5; layer++) {
        if (layer > 0)
            k_mma<HID, true><<<gemmB, 256, smem64>>>(p_h, Ws + (size_t)(layer - 1) * HID * HID,
                                                     p_hph, N);
        const float* bias  = (layer == 0) ? b1 : bs + (size_t)(layer - 1) * HID;
        const float* resid = (layer == 0) ? p_id : (layer < 4 ? p_h : nullptr);
        float*       hout  = (layer < 4) ? p_h : nullptr;
        const int*   bptr  = (layer == 4) ? batch : nullptr;
        k_agg<<<aggB, thr>>>(p_hph, resid, bias,
                             bn_g + layer * HID, bn_b + layer * HID,
                             bn_m + layer * HID, bn_v + layer * HID,
                             hout, bptr, N);
    }

    k_final<<<1, ((G + 31) / 32) * 32>>>(lin_w, lin_b, out, G);
}